// round 8
// baseline (speedup 1.0000x reference)
#include <cuda_runtime.h>
#include <cstdint>
#include <cstddef>

#define T_STEPS 2048
#define H_DIM   512
#define B_DIM   32
#define D_IN    128
#define ALPHA   0.1f

// ---------------------------------------------------------------------------
// Kernel 1: x_proj GEMM.  C[M,N] = A[M,K] * B[N,K]^T
//   A = x [65536,128], B = I [512,128], C = out [65536,512]
// BM=BN=128, BK=8, 256 threads, 8x8 microtile -> FFMA-bound.
// ---------------------------------------------------------------------------
__global__ __launch_bounds__(256) void xproj_gemm(const float* __restrict__ A,
                                                  const float* __restrict__ B,
                                                  float* __restrict__ C) {
    __shared__ float As[8][128];
    __shared__ float Bs[8][128];

    const int tid = threadIdx.x;
    const int bm  = blockIdx.x * 128;
    const int bn  = blockIdx.y * 128;

    const int lr = tid >> 1;          // row 0..127
    const int lc = (tid & 1) * 4;     // k offset 0 or 4
    const float* Ap = A + (size_t)(bm + lr) * D_IN + lc;
    const float* Bp = B + (size_t)(bn + lr) * D_IN + lc;

    const int tx = (tid & 15) * 8;
    const int ty = (tid >> 4) * 8;

    float acc[8][8] = {};

    for (int k0 = 0; k0 < D_IN; k0 += 8) {
        const float4 av = *(const float4*)(Ap + k0);
        const float4 bv = *(const float4*)(Bp + k0);
        __syncthreads();  // protect previous iteration's reads
        As[lc + 0][lr] = av.x; As[lc + 1][lr] = av.y;
        As[lc + 2][lr] = av.z; As[lc + 3][lr] = av.w;
        Bs[lc + 0][lr] = bv.x; Bs[lc + 1][lr] = bv.y;
        Bs[lc + 2][lr] = bv.z; Bs[lc + 3][lr] = bv.w;
        __syncthreads();

        #pragma unroll
        for (int k = 0; k < 8; k++) {
            float a[8], bb[8];
            *(float4*)&a[0]  = *(const float4*)&As[k][ty];
            *(float4*)&a[4]  = *(const float4*)&As[k][ty + 4];
            *(float4*)&bb[0] = *(const float4*)&Bs[k][tx];
            *(float4*)&bb[4] = *(const float4*)&Bs[k][tx + 4];
            #pragma unroll
            for (int i = 0; i < 8; i++)
                #pragma unroll
                for (int j = 0; j < 8; j++)
                    acc[i][j] = fmaf(a[i], bb[j], acc[i][j]);
        }
    }

    #pragma unroll
    for (int i = 0; i < 8; i++) {
        float* Cp = C + (size_t)(bm + ty + i) * H_DIM + bn + tx;
        *(float4*)(Cp)     = make_float4(acc[i][0], acc[i][1], acc[i][2], acc[i][3]);
        *(float4*)(Cp + 4) = make_float4(acc[i][4], acc[i][5], acc[i][6], acc[i][7]);
    }
}

// ---------------------------------------------------------------------------
// Kernel 2: sequential scan. ONE warp per batch, 16 h per thread.
// No barriers, no shared memory: the entire cross-h state per step (s0,s1)
// lives in a 5-level in-warp butterfly.
//
// Register budget (launch_bounds(32,1) -> 255 cap, no spills):
//   hs[16] + n0/n1/am0/am1[64] + xp depth-4 prefetch[64] + temps ~ 165.
// Layout: thread `lane` owns h = g*128 + lane*4 + k  (g=0..3, k=0..3)
//   -> 4x LDG.128 / 4x STG.128 per step, fully coalesced.
// out initially holds x_proj; overwritten in place (read of row t+4 is issued
// by the same thread, in program order, before that row's write at t+4).
// ---------------------------------------------------------------------------
__global__ __launch_bounds__(32, 1) void rnn_scan(const float* __restrict__ m,
                                                  const float* __restrict__ n,
                                                  float* __restrict__ out) {
    const int b    = blockIdx.x;
    const int lane = threadIdx.x;
    const float OMA = 1.0f - ALPHA;

    // per-h constants: h = g*128 + lane*4 + k
    float n0[16], n1[16], am0[16], am1[16];
    #pragma unroll
    for (int g = 0; g < 4; g++) {
        const int h0 = g * 128 + lane * 4;
        const float4 na = *(const float4*)(n + 2 * h0);
        const float4 nb = *(const float4*)(n + 2 * h0 + 4);
        const float4 ma = *(const float4*)(m + 2 * h0);
        const float4 mb = *(const float4*)(m + 2 * h0 + 4);
        n0[g*4+0] = na.x; n1[g*4+0] = na.y;
        n0[g*4+1] = na.z; n1[g*4+1] = na.w;
        n0[g*4+2] = nb.x; n1[g*4+2] = nb.y;
        n0[g*4+3] = nb.z; n1[g*4+3] = nb.w;
        am0[g*4+0] = ALPHA * ma.x; am1[g*4+0] = ALPHA * ma.y;
        am0[g*4+1] = ALPHA * ma.z; am1[g*4+1] = ALPHA * ma.w;
        am0[g*4+2] = ALPHA * mb.x; am1[g*4+2] = ALPHA * mb.y;
        am0[g*4+3] = ALPHA * mb.z; am1[g*4+3] = ALPHA * mb.w;
    }

    float* base = out + (size_t)b * T_STEPS * H_DIM + lane * 4;

    float hs[16];
    #pragma unroll
    for (int i = 0; i < 16; i++) hs[i] = 0.0f;

    // depth-4 prefetch of x_proj rows
    float4 xp[4][4];   // [depth][g]
    #pragma unroll
    for (int d = 0; d < 4; d++)
        #pragma unroll
        for (int g = 0; g < 4; g++)
            xp[d][g] = *(const float4*)(base + (size_t)d * H_DIM + g * 128);

    #pragma unroll 1
    for (int t = 0; t < T_STEPS; t += 4) {
        #pragma unroll
        for (int u = 0; u < 4; u++) {
            const int tt = t + u;

            // tanh consumed immediately into 4 accumulator chains (2 per comp)
            float q0a = 0.0f, q0b = 0.0f, q1a = 0.0f, q1b = 0.0f;
            #pragma unroll
            for (int i = 0; i < 16; i += 2) {
                float ta, tb;
                asm("tanh.approx.f32 %0, %1;" : "=f"(ta) : "f"(hs[i]));
                asm("tanh.approx.f32 %0, %1;" : "=f"(tb) : "f"(hs[i + 1]));
                q0a = fmaf(ta, n0[i],     q0a);
                q1a = fmaf(ta, n1[i],     q1a);
                q0b = fmaf(tb, n0[i + 1], q0b);
                q1b = fmaf(tb, n1[i + 1], q1b);
            }
            float p0 = q0a + q0b;
            float p1 = q1a + q1b;

            // in-place pre-update: hs <- (1-a)hs + a*xp   (tanh already taken)
            // overlaps the butterfly below
            #pragma unroll
            for (int g = 0; g < 4; g++) {
                const float4 x4 = xp[u][g];
                hs[g*4+0] = fmaf(ALPHA, x4.x, OMA * hs[g*4+0]);
                hs[g*4+1] = fmaf(ALPHA, x4.y, OMA * hs[g*4+1]);
                hs[g*4+2] = fmaf(ALPHA, x4.z, OMA * hs[g*4+2]);
                hs[g*4+3] = fmaf(ALPHA, x4.w, OMA * hs[g*4+3]);
            }

            // prefetch row tt+4 (off-chain)
            if (tt + 4 < T_STEPS) {
                #pragma unroll
                for (int g = 0; g < 4; g++)
                    xp[u][g] = *(const float4*)(base + (size_t)(tt + 4) * H_DIM + g * 128);
            }

            // full in-warp butterfly -> every lane gets (s0, s1)
            #pragma unroll
            for (int o = 16; o; o >>= 1) {
                p0 += __shfl_xor_sync(0xffffffffu, p0, o);
                p1 += __shfl_xor_sync(0xffffffffu, p1, o);
            }

            // finish update + store
            #pragma unroll
            for (int g = 0; g < 4; g++) {
                float4 o4;
                float* oe = (float*)&o4;
                #pragma unroll
                for (int k = 0; k < 4; k++) {
                    const int i = g * 4 + k;
                    hs[i] = fmaf(am0[i], p0, fmaf(am1[i], p1, hs[i]));
                    oe[k] = hs[i];
                }
                *(float4*)(base + (size_t)tt * H_DIM + g * 128) = o4;
            }
        }
    }
}

// ---------------------------------------------------------------------------
extern "C" void kernel_launch(void* const* d_in, const int* in_sizes, int n_in,
                              void* d_out, int out_size) {
    const float* x = (const float*)d_in[0];   // [32, 2048, 128]
    const float* m = (const float*)d_in[1];   // [512, 2]
    const float* n = (const float*)d_in[2];   // [512, 2]
    const float* I = (const float*)d_in[3];   // [512, 128]
    float* out = (float*)d_out;               // [32, 2048, 512]

    (void)in_sizes; (void)n_in; (void)out_size;

    dim3 ggrid((B_DIM * T_STEPS) / 128, H_DIM / 128);
    xproj_gemm<<<ggrid, 256>>>(x, I, out);
    rnn_scan<<<B_DIM, 32>>>(m, n, out);
}